// round 4
// baseline (speedup 1.0000x reference)
#include <cuda_runtime.h>
#include <cuda_bf16.h>

#define CONFIDENCE_F 0.95f
#define SMOOTHING_F  0.05f
#define B_MAX 65536
#define C_DIM 2048                 // floats per row
#define F4_PER_ROW (C_DIM / 4)     // 512 float4

// Deterministic per-row partials (loss_i, w_i) + completion counter.
__device__ float2 g_part[B_MAX];
__device__ unsigned int g_done = 0;   // reset to 0 by the last CTA each run

__global__ __launch_bounds__(256)
void ls_fused_kernel(const float4* __restrict__ x,
                     const int* __restrict__ t32,   // raw target words
                     const float* __restrict__ w,
                     float* __restrict__ out,
                     int B)
{
    const int warps_per_blk = blockDim.x >> 5;
    const int gwarp = blockIdx.x * warps_per_blk + (threadIdx.x >> 5);
    const int nwarp = gridDim.x * warps_per_blk;
    const int lane  = threadIdx.x & 31;

    // ---- Inline dtype detect (per-warp, deterministic) ----
    // int64 targets < 2048 => all odd words zero. Check 32 odd words:
    // P(all zero | int32 targets) = 2048^-32 ~ 0. L2-hot after first warp.
    int odd = t32[2 * lane + 1];
    unsigned int votes = __ballot_sync(0xffffffff, odd != 0);
    const bool is64 = (votes == 0u);

    // ---- Row loop: warp per row, x read exactly once ----
    for (int row = gwarp; row < B; row += nwarp) {
        const float4* xr = x + (size_t)row * F4_PER_ROW;

        float4 v[16];                       // front-batched, MLP = 16
        #pragma unroll
        for (int i = 0; i < 16; i++) v[i] = xr[lane + 32 * i];

        int ti = 0; float xt = 0.f, wt = 0.f;
        if (lane == 0) {
            ti = is64 ? (int)((const long long*)t32)[row] : t32[row];
            ti = min(max(ti, 0), C_DIM - 1);
            xt = ((const float*)x)[(size_t)row * C_DIM + ti];   // L1 hit
            wt = __ldg(&w[ti]);
        }

        float mx0 = -3.402823466e+38f, mx1 = mx0;
        float sx0 = 0.f, sx1 = 0.f;
        #pragma unroll
        for (int i = 0; i < 16; i += 2) {
            mx0 = fmaxf(mx0, fmaxf(fmaxf(v[i].x, v[i].y), fmaxf(v[i].z, v[i].w)));
            mx1 = fmaxf(mx1, fmaxf(fmaxf(v[i+1].x, v[i+1].y), fmaxf(v[i+1].z, v[i+1].w)));
            sx0 += (v[i].x + v[i].y) + (v[i].z + v[i].w);
            sx1 += (v[i+1].x + v[i+1].y) + (v[i+1].z + v[i+1].w);
        }
        float mx = fmaxf(mx0, mx1);
        float sx = sx0 + sx1;

        #pragma unroll
        for (int o = 16; o; o >>= 1)
            mx = fmaxf(mx, __shfl_xor_sync(0xffffffff, mx, o));

        float se0 = 0.f, se1 = 0.f;
        #pragma unroll
        for (int i = 0; i < 16; i += 2) {
            se0 += __expf(v[i].x - mx)   + __expf(v[i].y - mx)
                 + __expf(v[i].z - mx)   + __expf(v[i].w - mx);
            se1 += __expf(v[i+1].x - mx) + __expf(v[i+1].y - mx)
                 + __expf(v[i+1].z - mx) + __expf(v[i+1].w - mx);
        }
        float se = se0 + se1;

        #pragma unroll
        for (int o = 16; o; o >>= 1) {
            se += __shfl_xor_sync(0xffffffff, se, o);
            sx += __shfl_xor_sync(0xffffffff, sx, o);
        }

        if (lane == 0) {
            float lse    = mx + __logf(se);
            float nll    = lse - xt;                    // -logprob[target]
            float smooth = lse - sx * (1.0f / C_DIM);   // -mean(logprobs)
            g_part[row]  = make_float2(CONFIDENCE_F * nll * wt + SMOOTHING_F * smooth, wt);
        }
    }

    // ---- Last-CTA-done final reduction ----
    __shared__ bool am_last;
    __shared__ float2 s_red[8];

    __threadfence();                       // make g_part writes visible
    __syncthreads();
    if (threadIdx.x == 0) {
        unsigned int prev = atomicAdd(&g_done, 1u);
        am_last = (prev == gridDim.x - 1);
    }
    __syncthreads();
    if (!am_last) return;

    __threadfence();                       // acquire all CTAs' g_part writes

    const float4* p4 = (const float4*)g_part;   // 2 (loss,w) pairs per float4
    int npairs4 = B >> 1;
    float ls = 0.f, ws = 0.f;
    for (int i = threadIdx.x; i < npairs4; i += blockDim.x) {
        float4 p = p4[i];
        ls += p.x + p.z;
        ws += p.y + p.w;
    }
    if ((B & 1) && threadIdx.x == 0) {
        float2 p = g_part[B - 1];
        ls += p.x; ws += p.y;
    }
    #pragma unroll
    for (int o = 16; o; o >>= 1) {
        ls += __shfl_xor_sync(0xffffffff, ls, o);
        ws += __shfl_xor_sync(0xffffffff, ws, o);
    }
    int wid = threadIdx.x >> 5, lid = threadIdx.x & 31;
    if (lid == 0) s_red[wid] = make_float2(ls, ws);
    __syncthreads();
    if (threadIdx.x == 0) {
        float L = 0.f, W = 0.f;
        #pragma unroll
        for (int i = 0; i < 8; i++) { L += s_red[i].x; W += s_red[i].y; }
        out[0] = L / W;
        g_done = 0;                        // reset for deterministic graph replay
    }
}

extern "C" void kernel_launch(void* const* d_in, const int* in_sizes, int n_in,
                              void* d_out, int out_size)
{
    // Identify inputs by element count: x = largest, weight = smallest,
    // target = the remaining one.
    int ix = 0, it = 1, iw = 2;
    long long best = -1;
    for (int i = 0; i < n_in; i++)
        if ((long long)in_sizes[i] > best) { best = in_sizes[i]; ix = i; }
    long long small = best + 1;
    for (int i = 0; i < n_in; i++)
        if (i != ix && (long long)in_sizes[i] < small) { small = in_sizes[i]; iw = i; }
    for (int i = 0; i < n_in; i++)
        if (i != ix && i != iw) it = i;

    const float4* x   = (const float4*)d_in[ix];
    const int*    tgt = (const int*)d_in[it];
    const float*  w   = (const float*)d_in[iw];
    float* out = (float*)d_out;

    int B = in_sizes[ix] / C_DIM;
    if (B > B_MAX) B = B_MAX;

    int nblocks = (B + 31) / 32;           // 8 warps/block, 4 rows per warp
    if (nblocks < 1)    nblocks = 1;
    if (nblocks > 2048) nblocks = 2048;

    ls_fused_kernel<<<nblocks, 256>>>(x, tgt, w, out, B);
}

// round 5
// speedup vs baseline: 1.1133x; 1.1133x over previous
#include <cuda_runtime.h>
#include <cuda_bf16.h>

#define CONFIDENCE_F 0.95f
#define SMOOTHING_F  0.05f
#define B_MAX 65536
#define C_DIM 2048                 // floats per row
#define F4_PER_ROW (C_DIM / 4)     // 512 float4

// Deterministic per-row partials (loss_i, w_i). __device__ global scratch.
__device__ float2 g_part[B_MAX];

// Warp-per-row, chunked online softmax, double-buffered loads.
// Chunk = 4 float4 per thread (512 floats/warp); 4 chunks cover the row.
__global__ __launch_bounds__(256, 4)
void ls_row_kernel(const float4* __restrict__ x,
                   const int* __restrict__ t32,
                   const float* __restrict__ w,
                   int B)
{
    const int warps_per_blk = blockDim.x >> 5;
    const int gwarp = blockIdx.x * warps_per_blk + (threadIdx.x >> 5);
    const int nwarp = gridDim.x * warps_per_blk;
    const int lane  = threadIdx.x & 31;

    // Inline dtype detect: int64 targets < 2048 => odd words all zero.
    // 32 odd words checked => P(false int64 | int32 data) = 2048^-32 ~ 0.
    int oddw = t32[2 * lane + 1];
    const bool is64 = (__ballot_sync(0xffffffff, oddw != 0) == 0u);

    for (int row = gwarp; row < B; row += nwarp) {
        const float4* xr = x + (size_t)row * F4_PER_ROW;

        float4 a[4], b[4];
        // prologue: chunk 0
        #pragma unroll
        for (int j = 0; j < 4; j++) a[j] = xr[lane + 32 * j];

        // lane 0 side-fetch overlaps with chunk-0 wait
        int ti = 0; float wt = 0.f;
        if (lane == 0) {
            ti = is64 ? (int)((const long long*)t32)[row] : t32[row];
            ti = min(max(ti, 0), C_DIM - 1);
            wt = __ldg(&w[ti]);
        }

        float m = -3.402823466e+38f, s = 0.f, sx = 0.f;

        #pragma unroll
        for (int c = 0; c < 4; c++) {
            float4* cur = (c & 1) ? b : a;
            float4* nxt = (c & 1) ? a : b;
            if (c < 3) {                       // issue next chunk before compute
                #pragma unroll
                for (int j = 0; j < 4; j++)
                    nxt[j] = xr[lane + 32 * ((c + 1) * 4 + j)];
            }
            // chunk max
            float mc0 = fmaxf(fmaxf(cur[0].x, cur[0].y), fmaxf(cur[0].z, cur[0].w));
            float mc1 = fmaxf(fmaxf(cur[1].x, cur[1].y), fmaxf(cur[1].z, cur[1].w));
            float mc2 = fmaxf(fmaxf(cur[2].x, cur[2].y), fmaxf(cur[2].z, cur[2].w));
            float mc3 = fmaxf(fmaxf(cur[3].x, cur[3].y), fmaxf(cur[3].z, cur[3].w));
            float mc = fmaxf(fmaxf(mc0, mc1), fmaxf(mc2, mc3));
            float m2 = fmaxf(m, mc);
            // rescale running sum (first iter: exp(-huge)=0, s=0 -> ok)
            float e0 = 0.f, e1 = 0.f;
            #pragma unroll
            for (int j = 0; j < 4; j += 2) {
                e0 += __expf(cur[j].x - m2)   + __expf(cur[j].y - m2)
                    + __expf(cur[j].z - m2)   + __expf(cur[j].w - m2);
                e1 += __expf(cur[j+1].x - m2) + __expf(cur[j+1].y - m2)
                    + __expf(cur[j+1].z - m2) + __expf(cur[j+1].w - m2);
                sx += (cur[j].x + cur[j].y) + (cur[j].z + cur[j].w)
                    + (cur[j+1].x + cur[j+1].y) + (cur[j+1].z + cur[j+1].w);
            }
            s = s * __expf(m - m2) + (e0 + e1);
            m = m2;
        }

        // cross-lane combine: global max, rescale once, then sum
        float M = m;
        #pragma unroll
        for (int o = 16; o; o >>= 1)
            M = fmaxf(M, __shfl_xor_sync(0xffffffff, M, o));
        s *= __expf(m - M);
        #pragma unroll
        for (int o = 16; o; o >>= 1) {
            s  += __shfl_xor_sync(0xffffffff, s,  o);
            sx += __shfl_xor_sync(0xffffffff, sx, o);
        }

        if (lane == 0) {
            float xt = ((const float*)x)[(size_t)row * C_DIM + ti];  // L1/L2 hit
            float lse    = M + __logf(s);
            float nll    = lse - xt;                    // -logprob[target]
            float smooth = lse - sx * (1.0f / C_DIM);   // -mean(logprobs)
            g_part[row]  = make_float2(CONFIDENCE_F * nll * wt + SMOOTHING_F * smooth, wt);
        }
    }
}

__global__ __launch_bounds__(1024)
void ls_final_kernel(float* __restrict__ out, int nrows)
{
    __shared__ float2 s[32];
    const float4* p4 = (const float4*)g_part;   // two (loss,w) pairs per float4
    int npairs4 = nrows >> 1;
    float ls = 0.f, ws = 0.f;
    for (int i = threadIdx.x; i < npairs4; i += 1024) {
        float4 p = p4[i];
        ls += p.x + p.z;
        ws += p.y + p.w;
    }
    if ((nrows & 1) && threadIdx.x == 0) {
        float2 p = g_part[nrows - 1];
        ls += p.x; ws += p.y;
    }
    #pragma unroll
    for (int o = 16; o; o >>= 1) {
        ls += __shfl_xor_sync(0xffffffff, ls, o);
        ws += __shfl_xor_sync(0xffffffff, ws, o);
    }
    int wid = threadIdx.x >> 5, lid = threadIdx.x & 31;
    if (lid == 0) s[wid] = make_float2(ls, ws);
    __syncthreads();
    if (threadIdx.x == 0) {
        float L = 0.f, W = 0.f;
        #pragma unroll
        for (int i = 0; i < 32; i++) { L += s[i].x; W += s[i].y; }
        out[0] = L / W;
    }
}

extern "C" void kernel_launch(void* const* d_in, const int* in_sizes, int n_in,
                              void* d_out, int out_size)
{
    // Identify inputs by element count: x = largest, weight = smallest,
    // target = the remaining one.
    int ix = 0, it = 1, iw = 2;
    long long best = -1;
    for (int i = 0; i < n_in; i++)
        if ((long long)in_sizes[i] > best) { best = in_sizes[i]; ix = i; }
    long long small = best + 1;
    for (int i = 0; i < n_in; i++)
        if (i != ix && (long long)in_sizes[i] < small) { small = in_sizes[i]; iw = i; }
    for (int i = 0; i < n_in; i++)
        if (i != ix && i != iw) it = i;

    const float4* x   = (const float4*)d_in[ix];
    const int*    tgt = (const int*)d_in[it];
    const float*  w   = (const float*)d_in[iw];
    float* out = (float*)d_out;

    int B = in_sizes[ix] / C_DIM;
    if (B > B_MAX) B = B_MAX;

    int nblocks = (B + 31) / 32;           // 8 warps/block, ~4 rows per warp
    if (nblocks < 1)    nblocks = 1;
    if (nblocks > 2048) nblocks = 2048;

    ls_row_kernel<<<nblocks, 256>>>(x, tgt, w, B);
    ls_final_kernel<<<1, 1024>>>(out, B);
}

// round 6
// speedup vs baseline: 1.2350x; 1.1093x over previous
#include <cuda_runtime.h>
#include <cuda_bf16.h>

#define CONFIDENCE_F 0.95f
#define SMOOTHING_F  0.05f
#define C_DIM 2048                 // floats per row
#define F4_PER_ROW (C_DIM / 4)     // 512 float4
#define NBLOCKS 592                // 148 SMs x 4 CTAs, single wave
#define NBLOCKS_MAX 2048

// One (loss_sum, w_sum) partial per CTA. __device__ global scratch.
__device__ float2 g_cta[NBLOCKS_MAX];

// Warp-per-row, chunked online softmax, double-buffered loads with
// cross-row prefetch: the warp always has a chunk of loads in flight.
__global__ __launch_bounds__(256, 4)
void ls_row_kernel(const float4* __restrict__ x,
                   const int* __restrict__ t32,
                   const float* __restrict__ w,
                   int B)
{
    __shared__ float2 s_red[8];

    const int wid   = threadIdx.x >> 5;
    const int lane  = threadIdx.x & 31;
    const int gwarp = blockIdx.x * 8 + wid;
    const int nwarp = gridDim.x * 8;

    // Inline dtype detect: int64 targets < 2048 => odd words all zero.
    // 32 odd words checked => P(false int64 | int32 data) = 2048^-32 ~ 0.
    int oddw = t32[2 * lane + 1];
    const bool is64 = (__ballot_sync(0xffffffff, oddw != 0) == 0u);

    float loss_acc = 0.f, w_acc = 0.f;     // lane-0 accumulators (fixed order)

    float4 a[4], b[4];
    int row = gwarp;
    if (row < B) {                          // prologue: chunk 0 of first row
        const float4* xr = x + (size_t)row * F4_PER_ROW;
        #pragma unroll
        for (int j = 0; j < 4; j++) a[j] = xr[lane + 32 * j];
    }

    for (; row < B; row += nwarp) {
        const float4* xr = x + (size_t)row * F4_PER_ROW;
        const int nrow = row + nwarp;

        // lane-0 side fetches at row start: latency hidden under row compute
        int ti = 0; float wt = 0.f, xt = 0.f;
        if (lane == 0) {
            ti = is64 ? (int)((const long long*)t32)[row] : t32[row];
            ti = min(max(ti, 0), C_DIM - 1);
            wt = __ldg(&w[ti]);
            xt = ((const float*)xr)[ti];
        }

        float m = -3.402823466e+38f, s = 0.f, sx = 0.f;

        #pragma unroll
        for (int c = 0; c < 4; c++) {
            float4* cur = (c & 1) ? b : a;
            float4* nxt = (c & 1) ? a : b;
            if (c < 3) {                    // overlap: next chunk of this row
                #pragma unroll
                for (int j = 0; j < 4; j++)
                    nxt[j] = xr[lane + 32 * ((c + 1) * 4 + j)];
            } else if (nrow < B) {          // overlap: chunk 0 of NEXT row
                const float4* xn = x + (size_t)nrow * F4_PER_ROW;
                #pragma unroll
                for (int j = 0; j < 4; j++)
                    nxt[j] = xn[lane + 32 * j];
            }
            float mc0 = fmaxf(fmaxf(cur[0].x, cur[0].y), fmaxf(cur[0].z, cur[0].w));
            float mc1 = fmaxf(fmaxf(cur[1].x, cur[1].y), fmaxf(cur[1].z, cur[1].w));
            float mc2 = fmaxf(fmaxf(cur[2].x, cur[2].y), fmaxf(cur[2].z, cur[2].w));
            float mc3 = fmaxf(fmaxf(cur[3].x, cur[3].y), fmaxf(cur[3].z, cur[3].w));
            float m2 = fmaxf(m, fmaxf(fmaxf(mc0, mc1), fmaxf(mc2, mc3)));
            float e0 = 0.f, e1 = 0.f;
            #pragma unroll
            for (int j = 0; j < 4; j += 2) {
                e0 += __expf(cur[j].x - m2)   + __expf(cur[j].y - m2)
                    + __expf(cur[j].z - m2)   + __expf(cur[j].w - m2);
                e1 += __expf(cur[j+1].x - m2) + __expf(cur[j+1].y - m2)
                    + __expf(cur[j+1].z - m2) + __expf(cur[j+1].w - m2);
                sx += (cur[j].x + cur[j].y) + (cur[j].z + cur[j].w)
                    + (cur[j+1].x + cur[j+1].y) + (cur[j+1].z + cur[j+1].w);
            }
            s = s * __expf(m - m2) + (e0 + e1);
            m = m2;
        }

        // cross-lane combine (next row's chunk 0 is in flight during this)
        float M = m;
        #pragma unroll
        for (int o = 16; o; o >>= 1)
            M = fmaxf(M, __shfl_xor_sync(0xffffffff, M, o));
        s *= __expf(m - M);
        #pragma unroll
        for (int o = 16; o; o >>= 1) {
            s  += __shfl_xor_sync(0xffffffff, s,  o);
            sx += __shfl_xor_sync(0xffffffff, sx, o);
        }

        if (lane == 0) {
            float lse    = M + __logf(s);
            float nll    = lse - xt;                    // -logprob[target]
            float smooth = lse - sx * (1.0f / C_DIM);   // -mean(logprobs)
            loss_acc += CONFIDENCE_F * nll * wt + SMOOTHING_F * smooth;
            w_acc    += wt;
        }
    }

    // CTA reduction of 8 warp partials (fixed order -> deterministic)
    if (lane == 0) s_red[wid] = make_float2(loss_acc, w_acc);
    __syncthreads();
    if (threadIdx.x == 0) {
        float L = 0.f, W = 0.f;
        #pragma unroll
        for (int i = 0; i < 8; i++) { L += s_red[i].x; W += s_red[i].y; }
        g_cta[blockIdx.x] = make_float2(L, W);
    }
}

__global__ __launch_bounds__(256)
void ls_final_kernel(float* __restrict__ out, int ncta)
{
    __shared__ float2 s[8];
    float ls = 0.f, ws = 0.f;
    for (int i = threadIdx.x; i < ncta; i += blockDim.x) {
        float2 p = g_cta[i];
        ls += p.x; ws += p.y;
    }
    #pragma unroll
    for (int o = 16; o; o >>= 1) {
        ls += __shfl_xor_sync(0xffffffff, ls, o);
        ws += __shfl_xor_sync(0xffffffff, ws, o);
    }
    int wid = threadIdx.x >> 5, lid = threadIdx.x & 31;
    if (lid == 0) s[wid] = make_float2(ls, ws);
    __syncthreads();
    if (threadIdx.x == 0) {
        float L = 0.f, W = 0.f;
        #pragma unroll
        for (int i = 0; i < 8; i++) { L += s[i].x; W += s[i].y; }
        out[0] = L / W;
    }
}

extern "C" void kernel_launch(void* const* d_in, const int* in_sizes, int n_in,
                              void* d_out, int out_size)
{
    // Identify inputs by element count: x = largest, weight = smallest,
    // target = the remaining one.
    int ix = 0, it = 1, iw = 2;
    long long best = -1;
    for (int i = 0; i < n_in; i++)
        if ((long long)in_sizes[i] > best) { best = in_sizes[i]; ix = i; }
    long long small = best + 1;
    for (int i = 0; i < n_in; i++)
        if (i != ix && (long long)in_sizes[i] < small) { small = in_sizes[i]; iw = i; }
    for (int i = 0; i < n_in; i++)
        if (i != ix && i != iw) it = i;

    const float4* x   = (const float4*)d_in[ix];
    const int*    tgt = (const int*)d_in[it];
    const float*  w   = (const float*)d_in[iw];
    float* out = (float*)d_out;

    int B = in_sizes[ix] / C_DIM;

    int nblocks = NBLOCKS;                 // single persistent wave
    int nwarps_needed = B;                 // one row per warp minimum
    if (nwarps_needed < nblocks * 8) nblocks = (nwarps_needed + 7) / 8;
    if (nblocks < 1) nblocks = 1;
    if (nblocks > NBLOCKS_MAX) nblocks = NBLOCKS_MAX;

    ls_row_kernel<<<nblocks, 256>>>(x, tgt, w, B);
    ls_final_kernel<<<1, 256>>>(out, nblocks);
}

// round 7
// speedup vs baseline: 1.2697x; 1.0281x over previous
#include <cuda_runtime.h>
#include <cuda_bf16.h>

#define CONFIDENCE_F 0.95f
#define SMOOTHING_F  0.05f
#define C_DIM 2048                 // floats per row
#define F4_PER_ROW (C_DIM / 4)     // 512 float4
#define NBLOCKS 592                // 148 SMs x 4 CTAs, single wave
#define NBLOCKS_MAX 2048

// One (loss_sum, w_sum) partial per CTA + completion counter.
__device__ float2 g_cta[NBLOCKS_MAX];
__device__ unsigned int g_done = 0;    // reset by last CTA each run

// Warp-per-row, chunked online softmax, double-buffered loads with
// cross-row prefetch; last-CTA-done tail reduction (4.7 KB, L2-hot).
__global__ __launch_bounds__(256, 4)
void ls_row_kernel(const float4* __restrict__ x,
                   const int* __restrict__ t32,
                   const float* __restrict__ w,
                   float* __restrict__ out,
                   int B)
{
    __shared__ float2 s_red[8];
    __shared__ bool am_last;

    const int wid   = threadIdx.x >> 5;
    const int lane  = threadIdx.x & 31;
    const int gwarp = blockIdx.x * 8 + wid;
    const int nwarp = gridDim.x * 8;

    // Inline dtype detect: int64 targets < 2048 => odd words all zero.
    // 32 odd words checked => P(false int64 | int32 data) = 2048^-32 ~ 0.
    int oddw = t32[2 * lane + 1];
    const bool is64 = (__ballot_sync(0xffffffff, oddw != 0) == 0u);

    float loss_acc = 0.f, w_acc = 0.f;     // lane-0 accumulators (fixed order)

    float4 a[4], b[4];
    int row = gwarp;
    if (row < B) {                          // prologue: chunk 0 of first row
        const float4* xr = x + (size_t)row * F4_PER_ROW;
        #pragma unroll
        for (int j = 0; j < 4; j++) a[j] = xr[lane + 32 * j];
    }

    for (; row < B; row += nwarp) {
        const float4* xr = x + (size_t)row * F4_PER_ROW;
        const int nrow = row + nwarp;

        // lane-0 side fetches at row start: latency hidden under row compute
        int ti = 0; float wt = 0.f, xt = 0.f;
        if (lane == 0) {
            ti = is64 ? (int)((const long long*)t32)[row] : t32[row];
            ti = min(max(ti, 0), C_DIM - 1);
            wt = __ldg(&w[ti]);
            xt = ((const float*)xr)[ti];
        }

        float m = -3.402823466e+38f, s = 0.f, sx = 0.f;

        #pragma unroll
        for (int c = 0; c < 4; c++) {
            float4* cur = (c & 1) ? b : a;
            float4* nxt = (c & 1) ? a : b;
            if (c < 3) {                    // overlap: next chunk of this row
                #pragma unroll
                for (int j = 0; j < 4; j++)
                    nxt[j] = xr[lane + 32 * ((c + 1) * 4 + j)];
            } else if (nrow < B) {          // overlap: chunk 0 of NEXT row
                const float4* xn = x + (size_t)nrow * F4_PER_ROW;
                #pragma unroll
                for (int j = 0; j < 4; j++)
                    nxt[j] = xn[lane + 32 * j];
            }
            float mc0 = fmaxf(fmaxf(cur[0].x, cur[0].y), fmaxf(cur[0].z, cur[0].w));
            float mc1 = fmaxf(fmaxf(cur[1].x, cur[1].y), fmaxf(cur[1].z, cur[1].w));
            float mc2 = fmaxf(fmaxf(cur[2].x, cur[2].y), fmaxf(cur[2].z, cur[2].w));
            float mc3 = fmaxf(fmaxf(cur[3].x, cur[3].y), fmaxf(cur[3].z, cur[3].w));
            float m2 = fmaxf(m, fmaxf(fmaxf(mc0, mc1), fmaxf(mc2, mc3)));
            float e0 = 0.f, e1 = 0.f;
            #pragma unroll
            for (int j = 0; j < 4; j += 2) {
                e0 += __expf(cur[j].x - m2)   + __expf(cur[j].y - m2)
                    + __expf(cur[j].z - m2)   + __expf(cur[j].w - m2);
                e1 += __expf(cur[j+1].x - m2) + __expf(cur[j+1].y - m2)
                    + __expf(cur[j+1].z - m2) + __expf(cur[j+1].w - m2);
                sx += (cur[j].x + cur[j].y) + (cur[j].z + cur[j].w)
                    + (cur[j+1].x + cur[j+1].y) + (cur[j+1].z + cur[j+1].w);
            }
            s = s * __expf(m - m2) + (e0 + e1);
            m = m2;
        }

        // cross-lane combine (next row's chunk 0 is in flight during this)
        float M = m;
        #pragma unroll
        for (int o = 16; o; o >>= 1)
            M = fmaxf(M, __shfl_xor_sync(0xffffffff, M, o));
        s *= __expf(m - M);
        #pragma unroll
        for (int o = 16; o; o >>= 1) {
            s  += __shfl_xor_sync(0xffffffff, s,  o);
            sx += __shfl_xor_sync(0xffffffff, sx, o);
        }

        if (lane == 0) {
            float lse    = M + __logf(s);
            float nll    = lse - xt;                    // -logprob[target]
            float smooth = lse - sx * (1.0f / C_DIM);   // -mean(logprobs)
            loss_acc += CONFIDENCE_F * nll * wt + SMOOTHING_F * smooth;
            w_acc    += wt;
        }
    }

    // CTA reduction of 8 warp partials (fixed order -> deterministic)
    if (lane == 0) s_red[wid] = make_float2(loss_acc, w_acc);
    __syncthreads();
    if (threadIdx.x == 0) {
        float L = 0.f, W = 0.f;
        #pragma unroll
        for (int i = 0; i < 8; i++) { L += s_red[i].x; W += s_red[i].y; }
        g_cta[blockIdx.x] = make_float2(L, W);
        __threadfence();                   // publish partial before arriving
        unsigned int prev = atomicAdd(&g_done, 1u);
        am_last = (prev == gridDim.x - 1);
    }
    __syncthreads();
    if (!am_last) return;

    // ---- last CTA: reduce gridDim.x partials (L2-hot) ----
    __threadfence();                       // acquire all partials
    float ls = 0.f, ws = 0.f;
    for (int i = threadIdx.x; i < gridDim.x; i += blockDim.x) {
        float2 p = g_cta[i];
        ls += p.x; ws += p.y;
    }
    #pragma unroll
    for (int o = 16; o; o >>= 1) {
        ls += __shfl_xor_sync(0xffffffff, ls, o);
        ws += __shfl_xor_sync(0xffffffff, ws, o);
    }
    if (lane == 0) s_red[wid] = make_float2(ls, ws);
    __syncthreads();
    if (threadIdx.x == 0) {
        float L = 0.f, W = 0.f;
        #pragma unroll
        for (int i = 0; i < 8; i++) { L += s_red[i].x; W += s_red[i].y; }
        out[0] = L / W;
        g_done = 0;                        // deterministic graph replay
    }
}

extern "C" void kernel_launch(void* const* d_in, const int* in_sizes, int n_in,
                              void* d_out, int out_size)
{
    // Identify inputs by element count: x = largest, weight = smallest,
    // target = the remaining one.
    int ix = 0, it = 1, iw = 2;
    long long best = -1;
    for (int i = 0; i < n_in; i++)
        if ((long long)in_sizes[i] > best) { best = in_sizes[i]; ix = i; }
    long long small = best + 1;
    for (int i = 0; i < n_in; i++)
        if (i != ix && (long long)in_sizes[i] < small) { small = in_sizes[i]; iw = i; }
    for (int i = 0; i < n_in; i++)
        if (i != ix && i != iw) it = i;

    const float4* x   = (const float4*)d_in[ix];
    const int*    tgt = (const int*)d_in[it];
    const float*  w   = (const float*)d_in[iw];
    float* out = (float*)d_out;

    int B = in_sizes[ix] / C_DIM;

    int nblocks = NBLOCKS;                 // single persistent wave
    if (B < nblocks * 8) nblocks = (B + 7) / 8;
    if (nblocks < 1) nblocks = 1;
    if (nblocks > NBLOCKS_MAX) nblocks = NBLOCKS_MAX;

    ls_row_kernel<<<nblocks, 256>>>(x, tgt, w, out, B);
}